// round 14
// baseline (speedup 1.0000x reference)
#include <cuda_runtime.h>

// out[t, :] = W[seq[t], :] + W[pre[t], :] + W[post[t], :]
// D = 128 floats (512B row); lane l -> float4 #l; warp covers a full row.
// Scored timing is WARM-cache graph replay (51MB table stays L2-resident),
// where occupancy beats per-thread MLP (R13 evidence: 40-reg/6-CTA variant
// lost 25% on cold-ncu but won on warm wall). This round: TPW=2 @ 32 regs
// -> 8 CTAs/SM (64 warps, full occ), single wave = 148*8 = 1184 blocks.
// 6 live float4 = 24 regs, fits 32 with no spill: MLP=6 truly batched.

#define EMBED_VEC 32
#define THREADS_PER_BLOCK 256
#define WARPS_PER_BLOCK (THREADS_PER_BLOCK / 32)
#define TPW 2                 // tokens per warp-chunk
#define GRID_BLOCKS 1184      // 148 SMs * 8 resident CTAs (32-reg budget)

__global__ __launch_bounds__(THREADS_PER_BLOCK, 8)
void cbow_subword_kernel(const int* __restrict__ seq,
                         const int* __restrict__ pre,
                         const int* __restrict__ post,
                         const float4* __restrict__ W,
                         float4* __restrict__ out,
                         int n_tok) {
    const int warp = blockIdx.x * WARPS_PER_BLOCK + (threadIdx.x >> 5);
    const int lane = threadIdx.x & 31;
    const int n_warps = gridDim.x * WARPS_PER_BLOCK;
    const long long chunk_stride = (long long)n_warps * TPW;

    for (long long t0 = (long long)warp * TPW; t0 < n_tok; t0 += chunk_stride) {
        if (t0 + TPW <= n_tok) {
            // Vectorized index broadcasts (t0 is 2-aligned).
            int2 s = __ldg((const int2*)(seq  + t0));
            int2 p = __ldg((const int2*)(pre  + t0));
            int2 q = __ldg((const int2*)(post + t0));
            int ia[TPW] = {s.x, s.y};
            int ib[TPW] = {p.x, p.y};
            int ic[TPW] = {q.x, q.y};

            // 6 independent gathers issued before first use (MLP=6).
            float4 va[TPW], vb[TPW], vc[TPW];
            #pragma unroll
            for (int j = 0; j < TPW; j++) va[j] = __ldg(W + (size_t)ia[j] * EMBED_VEC + lane);
            #pragma unroll
            for (int j = 0; j < TPW; j++) vb[j] = __ldg(W + (size_t)ib[j] * EMBED_VEC + lane);
            #pragma unroll
            for (int j = 0; j < TPW; j++) vc[j] = __ldg(W + (size_t)ic[j] * EMBED_VEC + lane);

            #pragma unroll
            for (int j = 0; j < TPW; j++) {
                float4 r;
                r.x = va[j].x + vb[j].x + vc[j].x;
                r.y = va[j].y + vb[j].y + vc[j].y;
                r.z = va[j].z + vb[j].z + vc[j].z;
                r.w = va[j].w + vb[j].w + vc[j].w;
                // Streaming store: keep the 51MB weight table L2-resident.
                __stcs(out + (size_t)(t0 + j) * EMBED_VEC + lane, r);
            }
        } else {
            for (long long t = t0; t < n_tok; t++) {
                int i0 = __ldg(seq + t), i1 = __ldg(pre + t), i2 = __ldg(post + t);
                float4 a = __ldg(W + (size_t)i0 * EMBED_VEC + lane);
                float4 b = __ldg(W + (size_t)i1 * EMBED_VEC + lane);
                float4 c = __ldg(W + (size_t)i2 * EMBED_VEC + lane);
                float4 r;
                r.x = a.x + b.x + c.x;
                r.y = a.y + b.y + c.y;
                r.z = a.z + b.z + c.z;
                r.w = a.w + b.w + c.w;
                __stcs(out + (size_t)t * EMBED_VEC + lane, r);
            }
        }
    }
}

extern "C" void kernel_launch(void* const* d_in, const int* in_sizes, int n_in,
                              void* d_out, int out_size) {
    const int*    seq  = (const int*)d_in[0];
    const int*    pre  = (const int*)d_in[1];
    const int*    post = (const int*)d_in[2];
    const float4* W    = (const float4*)d_in[3];
    float4*       out  = (float4*)d_out;

    int n_tok = in_sizes[0];  // 131072

    // Single-wave persistent grid; shrink for tiny inputs.
    int chunks = (n_tok + TPW - 1) / TPW;
    int blocks_needed = (chunks + WARPS_PER_BLOCK - 1) / WARPS_PER_BLOCK;
    int blocks = GRID_BLOCKS < blocks_needed ? GRID_BLOCKS : blocks_needed;
    if (blocks < 1) blocks = 1;

    cbow_subword_kernel<<<blocks, THREADS_PER_BLOCK>>>(seq, pre, post, W, out, n_tok);
}